// round 6
// baseline (speedup 1.0000x reference)
#include <cuda_runtime.h>

// Problem constants (fixed by the reference)
#define NB   4
#define CC   128
#define HH   50
#define WW   50
#define RR   256
#define PHN  7
#define PWN  7
#define HW   (HH*WW)
#define SCALE 0.0625f

// fl(1/7) in f32 = 0x3E124925 = 0x1.24924ap-3. XLA rewrites x/7 -> x * fl(1/7);
// we replicate that exact chain: bin = fl(roi * fl(1/7)), then fl(m * bin).
#define RECIP7 0x1.24924ap-3f

// ---------------------------------------------------------------------------
// RoI max-pool, NCHW direct, listing semantics with reciprocal-multiply bins.
// grid: (7, 256) -> blockIdx.x = ph, blockIdx.y = roi; 128 threads = channels.
// ---------------------------------------------------------------------------
__global__ void __launch_bounds__(128)
roipool_kernel(const float* __restrict__ feat,
               const float* __restrict__ rois,
               float* __restrict__ out) {
    const int r  = blockIdx.y;
    const int ph = blockIdx.x;
    const int c  = threadIdx.x;

    const float* rp = rois + r * 5;
    const int b  = (int)rp[0];
    const int xs = (int)rintf(__fmul_rn(rp[1], SCALE));   // exact; RNE == jnp.round
    const int ys = (int)rintf(__fmul_rn(rp[2], SCALE));
    const int xe = (int)rintf(__fmul_rn(rp[3], SCALE));
    const int ye = (int)rintf(__fmul_rn(rp[4], SCALE));

    const float roi_w = (float)max(xe - xs + 1, 1);
    const float roi_h = (float)max(ye - ys + 1, 1);
    // Reciprocal-multiply division, exactly as XLA compiles roi/7:
    const float bin_h = __fmul_rn(roi_h, RECIP7);
    const float bin_w = __fmul_rn(roi_w, RECIP7);

    int hstart = (int)floorf(__fmul_rn((float)ph,       bin_h)) + ys;
    int hend   = (int)ceilf (__fmul_rn((float)(ph + 1), bin_h)) + ys;
    hstart = min(max(hstart, 0), HH);
    hend   = min(max(hend,   0), HH);

    const float* fb = feat + ((size_t)b * CC + c) * HW;     // NCHW (b,c) plane
    float* op = out + (((size_t)r * CC + c) * PHN + ph) * PWN;  // (R,C,7,7)

    #pragma unroll
    for (int pw = 0; pw < PWN; pw++) {
        int wstart = (int)floorf(__fmul_rn((float)pw,       bin_w)) + xs;
        int wend   = (int)ceilf (__fmul_rn((float)(pw + 1), bin_w)) + xs;
        wstart = min(max(wstart, 0), WW);
        wend   = min(max(wend,   0), WW);

        const bool any = (hend > hstart) && (wend > wstart);
        float m = -3.4e38f;
        for (int y = hstart; y < hend; y++) {
            const float* row = fb + y * WW;
            for (int x = wstart; x < wend; x++) {
                m = fmaxf(m, __ldg(row + x));
            }
        }
        op[pw] = any ? m : 0.0f;   // listing-empty -> 0 (validated in round 5)
    }
}

// ---------------------------------------------------------------------------
extern "C" void kernel_launch(void* const* d_in, const int* in_sizes, int n_in,
                              void* d_out, int out_size) {
    const float* feat = (const float*)d_in[0];   // (4,128,50,50)
    const float* rois = (const float*)d_in[1];   // (256,5)

    if (n_in >= 2 && in_sizes[0] == 1280 && in_sizes[1] == 1280000) {
        const float* t = feat; feat = rois; rois = t;   // defensive (never fires)
    }

    float* out = (float*)d_out;                  // (256,128,7,7)
    roipool_kernel<<<dim3(PHN, RR), CC>>>(feat, rois, out);
}

// round 8
// speedup vs baseline: 1.8317x; 1.8317x over previous
#include <cuda_runtime.h>

// Problem constants (fixed by the reference)
#define NB   4
#define CC   128
#define HH   50
#define WW   50
#define RR   256
#define PHN  7
#define PWN  7
#define HW   (HH*WW)        // 2500
#define SCALE 0.0625f

// fl(1/7) in f32 = 0x3E124925. XLA rewrites x/7 -> x * fl(1/7). Bit-exact match.
#define RECIP7 0x1.24924ap-3f

// NHWC scratch: 4*2500*128 floats = 5.12 MB (static device global — legal)
__device__ float g_featT[NB * HW * CC];

// ---------------------------------------------------------------------------
// Transpose NCHW -> NHWC. Per image: 128 x 2500 matrix transpose.
// grid: (ceil(2500/32)=79, 4, 4)   block: (32, 8)
// ---------------------------------------------------------------------------
__global__ void nchw_to_nhwc(const float* __restrict__ feat) {
    __shared__ float tile[32][33];
    const int n  = blockIdx.z;
    const int c0 = blockIdx.y * 32;
    const int s0 = blockIdx.x * 32;
    const float* src = feat    + (size_t)n * CC * HW;
    float*       dst = g_featT + (size_t)n * HW * CC;

    const int tx = threadIdx.x, ty = threadIdx.y;

    #pragma unroll
    for (int i = 0; i < 32; i += 8) {
        int s = s0 + tx;
        if (s < HW) tile[ty + i][tx] = src[(c0 + ty + i) * HW + s];
    }
    __syncthreads();
    #pragma unroll
    for (int i = 0; i < 32; i += 8) {
        int s = s0 + ty + i;
        if (s < HW) dst[s * CC + (c0 + tx)] = tile[tx][ty + i];
    }
}

// ---------------------------------------------------------------------------
// RoI max-pool on NHWC features.
// grid: (7, 256) -> blockIdx.x = ph, blockIdx.y = roi; 128 threads = channels.
// Gathers are fully coalesced (512B per block access). Results staged in
// padded shared memory, then written cooperatively to cut store wavefronts.
// Bin math is bit-identical to XLA (reciprocal-multiply, RNE decode).
// ---------------------------------------------------------------------------
__global__ void __launch_bounds__(128)
roipool_kernel(const float* __restrict__ rois, float* __restrict__ out) {
    __shared__ float stage[CC * 9];   // [c][pw], stride 9 (coprime w/ 32 banks)

    const int r  = blockIdx.y;
    const int ph = blockIdx.x;
    const int c  = threadIdx.x;

    const float* rp = rois + r * 5;
    const int b  = (int)rp[0];
    const int xs = (int)rintf(__fmul_rn(rp[1], SCALE));
    const int ys = (int)rintf(__fmul_rn(rp[2], SCALE));
    const int xe = (int)rintf(__fmul_rn(rp[3], SCALE));
    const int ye = (int)rintf(__fmul_rn(rp[4], SCALE));

    const float roi_w = (float)max(xe - xs + 1, 1);
    const float roi_h = (float)max(ye - ys + 1, 1);
    const float bin_h = __fmul_rn(roi_h, RECIP7);   // == XLA roi_h / 7
    const float bin_w = __fmul_rn(roi_w, RECIP7);

    int hstart = (int)floorf(__fmul_rn((float)ph,       bin_h)) + ys;
    int hend   = (int)ceilf (__fmul_rn((float)(ph + 1), bin_h)) + ys;
    hstart = min(max(hstart, 0), HH);
    hend   = min(max(hend,   0), HH);

    const float* base = g_featT + (size_t)b * HW * CC + c;   // NHWC, channel c

    #pragma unroll
    for (int pw = 0; pw < PWN; pw++) {
        int wstart = (int)floorf(__fmul_rn((float)pw,       bin_w)) + xs;
        int wend   = (int)ceilf (__fmul_rn((float)(pw + 1), bin_w)) + xs;
        wstart = min(max(wstart, 0), WW);
        wend   = min(max(wend,   0), WW);

        const bool any = (hend > hstart) && (wend > wstart);
        float m = -3.4e38f;
        for (int y = hstart; y < hend; y++) {
            const float* row = base + (size_t)(y * WW + wstart) * CC;
            for (int x = wstart; x < wend; x++) {
                m = fmaxf(m, __ldg(row));
                row += CC;
            }
        }
        stage[c * 9 + pw] = any ? m : 0.0f;
    }
    __syncthreads();

    // Cooperative write of the 128x7 tile: out[(r*128+cc)*49 + ph*7 + pww]
    float* ob = out + ((size_t)r * CC * PHN * PWN) + ph * PWN;
    #pragma unroll
    for (int e = c; e < CC * PWN; e += CC) {
        int cc  = e / PWN;        // compiler turns into mul-shift
        int pww = e - cc * PWN;
        ob[cc * (PHN * PWN) + pww] = stage[cc * 9 + pww];
    }
}

// ---------------------------------------------------------------------------
extern "C" void kernel_launch(void* const* d_in, const int* in_sizes, int n_in,
                              void* d_out, int out_size) {
    const float* feat = (const float*)d_in[0];   // (4,128,50,50)
    const float* rois = (const float*)d_in[1];   // (256,5)
    float* out = (float*)d_out;                  // (256,128,7,7)

    dim3 tb(32, 8);
    dim3 tg((HW + 31) / 32, CC / 32, NB);        // (79, 4, 4)
    nchw_to_nhwc<<<tg, tb>>>(feat);

    roipool_kernel<<<dim3(PHN, RR), CC>>>(rois, out);
}

// round 9
// speedup vs baseline: 2.8774x; 1.5709x over previous
#include <cuda_runtime.h>

// Problem constants (fixed by the reference)
#define NB   4
#define CC   128
#define HH   50
#define WW   50
#define RR   256
#define PHN  7
#define PWN  7
#define HW   (HH*WW)        // 2500
#define SCALE 0.0625f

// fl(1/7) in f32 = 0x3E124925. XLA rewrites x/7 -> x * fl(1/7). Bit-exact match.
#define RECIP7 0x1.24924ap-3f

// NHWC scratch as float4 quads: 4*2500*32 float4 = 5.12 MB, 16B-aligned.
__device__ float4 g_featT4[NB * HW * (CC / 4)];

// ---------------------------------------------------------------------------
// Transpose NCHW -> NHWC. Per image: 128 x 2500 matrix transpose.
// grid: (79, 4, 4)   block: (32, 8)
// ---------------------------------------------------------------------------
__global__ void nchw_to_nhwc(const float* __restrict__ feat) {
    __shared__ float tile[32][33];
    const int n  = blockIdx.z;
    const int c0 = blockIdx.y * 32;
    const int s0 = blockIdx.x * 32;
    const float* src = feat + (size_t)n * CC * HW;
    float*       dst = (float*)g_featT4 + (size_t)n * HW * CC;

    const int tx = threadIdx.x, ty = threadIdx.y;

    #pragma unroll
    for (int i = 0; i < 32; i += 8) {
        int s = s0 + tx;
        if (s < HW) tile[ty + i][tx] = src[(c0 + ty + i) * HW + s];
    }
    __syncthreads();
    #pragma unroll
    for (int i = 0; i < 32; i += 8) {
        int s = s0 + ty + i;
        if (s < HW) dst[s * CC + (c0 + tx)] = tile[tx][ty + i];
    }
}

// ---------------------------------------------------------------------------
// RoI max-pool on NHWC features, float4-vectorized over channels.
// grid: (7, 256) -> blockIdx.x = ph, blockIdx.y = roi.
// block: 128 = 4 warps x 32 lanes. lane = channel quad (4 channels),
// warp w handles pw in {w, w+4}. Each warp load = contiguous 512B.
// ---------------------------------------------------------------------------
__global__ void __launch_bounds__(128)
roipool_kernel(const float* __restrict__ rois, float* __restrict__ out) {
    __shared__ float4 stage4[PWN][33];   // [pw][lane], padded (33)

    const int r  = blockIdx.y;
    const int ph = blockIdx.x;
    const int w  = threadIdx.x >> 5;     // warp id
    const int l  = threadIdx.x & 31;     // lane = channel quad

    const float* rp = rois + r * 5;
    const int b  = (int)rp[0];
    const int xs = (int)rintf(__fmul_rn(rp[1], SCALE));
    const int ys = (int)rintf(__fmul_rn(rp[2], SCALE));
    const int xe = (int)rintf(__fmul_rn(rp[3], SCALE));
    const int ye = (int)rintf(__fmul_rn(rp[4], SCALE));

    const float roi_w = (float)max(xe - xs + 1, 1);
    const float roi_h = (float)max(ye - ys + 1, 1);
    const float bin_h = __fmul_rn(roi_h, RECIP7);   // == XLA roi_h / 7
    const float bin_w = __fmul_rn(roi_w, RECIP7);

    int hstart = (int)floorf(__fmul_rn((float)ph,       bin_h)) + ys;
    int hend   = (int)ceilf (__fmul_rn((float)(ph + 1), bin_h)) + ys;
    hstart = min(max(hstart, 0), HH);
    hend   = min(max(hend,   0), HH);

    const float4* base = g_featT4 + (size_t)b * HW * (CC / 4) + l;

    for (int pw = w; pw < PWN; pw += 4) {
        int wstart = (int)floorf(__fmul_rn((float)pw,       bin_w)) + xs;
        int wend   = (int)ceilf (__fmul_rn((float)(pw + 1), bin_w)) + xs;
        wstart = min(max(wstart, 0), WW);
        wend   = min(max(wend,   0), WW);

        const bool any = (hend > hstart) && (wend > wstart);
        float4 m = make_float4(-3.4e38f, -3.4e38f, -3.4e38f, -3.4e38f);
        for (int y = hstart; y < hend; y++) {
            const float4* row = base + (size_t)(y * WW + wstart) * (CC / 4);
            #pragma unroll 4
            for (int x = wstart; x < wend; x++) {
                float4 v = __ldg(row);
                m.x = fmaxf(m.x, v.x);
                m.y = fmaxf(m.y, v.y);
                m.z = fmaxf(m.z, v.z);
                m.w = fmaxf(m.w, v.w);
                row += (CC / 4);
            }
        }
        if (!any) m = make_float4(0.f, 0.f, 0.f, 0.f);
        stage4[pw][l] = m;
    }
    __syncthreads();

    // Copy out the 128x7 tile: out[(r*128+c)*49 + ph*7 + pw]
    // stage float view: channel c of bin pw lives at float index pw*132 + c.
    const float* sf = (const float*)stage4;
    float* ob = out + (size_t)r * CC * (PHN * PWN) + ph * PWN;
    #pragma unroll
    for (int e = threadIdx.x; e < CC * PWN; e += 128) {
        int c  = e / PWN;
        int pw = e - c * PWN;
        ob[c * (PHN * PWN) + pw] = sf[pw * 132 + c];
    }
}

// ---------------------------------------------------------------------------
extern "C" void kernel_launch(void* const* d_in, const int* in_sizes, int n_in,
                              void* d_out, int out_size) {
    const float* feat = (const float*)d_in[0];   // (4,128,50,50)
    const float* rois = (const float*)d_in[1];   // (256,5)
    float* out = (float*)d_out;                  // (256,128,7,7)

    dim3 tb(32, 8);
    dim3 tg((HW + 31) / 32, CC / 32, NB);        // (79, 4, 4)
    nchw_to_nhwc<<<tg, tb>>>(feat);

    roipool_kernel<<<dim3(PHN, RR), 128>>>(rois, out);
}

// round 10
// speedup vs baseline: 3.6592x; 1.2717x over previous
#include <cuda_runtime.h>

// Problem constants (fixed by the reference)
#define NB   4
#define CC   128
#define HH   50
#define WW   50
#define RR   256
#define PHN  7
#define PWN  7
#define HW   (HH*WW)        // 2500
#define SCALE 0.0625f

// fl(1/7) in f32 = 0x3E124925. XLA rewrites x/7 -> x * fl(1/7). Bit-exact match.
#define RECIP7 0x1.24924ap-3f

// NHWC scratch as float4 quads: 4*2500*32 float4 = 5.12 MB, 16B-aligned.
__device__ float4 g_featT4[NB * HW * (CC / 4)];

// ---------------------------------------------------------------------------
// Transpose NCHW -> NHWC. Per image: 128 x 2500 matrix transpose.
// grid: (79, 4, 4)   block: (32, 8)
// ---------------------------------------------------------------------------
__global__ void nchw_to_nhwc(const float* __restrict__ feat) {
    __shared__ float tile[32][33];
    const int n  = blockIdx.z;
    const int c0 = blockIdx.y * 32;
    const int s0 = blockIdx.x * 32;
    const float* src = feat + (size_t)n * CC * HW;
    float*       dst = (float*)g_featT4 + (size_t)n * HW * CC;

    const int tx = threadIdx.x, ty = threadIdx.y;

    #pragma unroll
    for (int i = 0; i < 32; i += 8) {
        int s = s0 + tx;
        if (s < HW) tile[ty + i][tx] = src[(c0 + ty + i) * HW + s];
    }
    __syncthreads();
    #pragma unroll
    for (int i = 0; i < 32; i += 8) {
        int s = s0 + ty + i;
        if (s < HW) dst[s * CC + (c0 + tx)] = tile[tx][ty + i];
    }
}

// ---------------------------------------------------------------------------
// RoI max-pool on NHWC features, float4 channels, ONE WARP PER BIN.
// grid: (7, 256) -> blockIdx.x = ph, blockIdx.y = roi.
// block: 224 = 7 warps; warp w owns bin pw=w; lane = channel quad.
// Dual y-row accumulators double the MLP of the max chain.
// ---------------------------------------------------------------------------
__global__ void __launch_bounds__(224)
roipool_kernel(const float* __restrict__ rois, float* __restrict__ out) {
    __shared__ float4 stage4[PWN][33];   // [pw][lane], padded

    const int r  = blockIdx.y;
    const int ph = blockIdx.x;
    const int pw = threadIdx.x >> 5;     // warp id == pw bin
    const int l  = threadIdx.x & 31;     // lane = channel quad

    const float* rp = rois + r * 5;
    const int b  = (int)rp[0];
    const int xs = (int)rintf(__fmul_rn(rp[1], SCALE));
    const int ys = (int)rintf(__fmul_rn(rp[2], SCALE));
    const int xe = (int)rintf(__fmul_rn(rp[3], SCALE));
    const int ye = (int)rintf(__fmul_rn(rp[4], SCALE));

    const float roi_w = (float)max(xe - xs + 1, 1);
    const float roi_h = (float)max(ye - ys + 1, 1);
    const float bin_h = __fmul_rn(roi_h, RECIP7);   // == XLA roi_h / 7
    const float bin_w = __fmul_rn(roi_w, RECIP7);

    int hstart = (int)floorf(__fmul_rn((float)ph,       bin_h)) + ys;
    int hend   = (int)ceilf (__fmul_rn((float)(ph + 1), bin_h)) + ys;
    hstart = min(max(hstart, 0), HH);
    hend   = min(max(hend,   0), HH);

    int wstart = (int)floorf(__fmul_rn((float)pw,       bin_w)) + xs;
    int wend   = (int)ceilf (__fmul_rn((float)(pw + 1), bin_w)) + xs;
    wstart = min(max(wstart, 0), WW);
    wend   = min(max(wend,   0), WW);

    const bool any = (hend > hstart) && (wend > wstart);
    const int cols = wend - wstart;
    const float4* base = g_featT4 + ((size_t)b * HW + wstart) * (CC / 4) + l;

    const float NEG = -3.4e38f;
    float4 m0 = make_float4(NEG, NEG, NEG, NEG);
    float4 m1 = m0;

    // Two independent accumulator chains over alternating rows (2x MLP).
    for (int y = hstart; y + 1 < hend; y += 2) {
        const float4* ra = base + (size_t)(y * WW) * (CC / 4);
        const float4* rb = ra + (size_t)WW * (CC / 4);
        #pragma unroll 4
        for (int x = 0; x < cols; x++) {
            float4 va = __ldg(ra); ra += (CC / 4);
            float4 vb = __ldg(rb); rb += (CC / 4);
            m0.x = fmaxf(m0.x, va.x); m0.y = fmaxf(m0.y, va.y);
            m0.z = fmaxf(m0.z, va.z); m0.w = fmaxf(m0.w, va.w);
            m1.x = fmaxf(m1.x, vb.x); m1.y = fmaxf(m1.y, vb.y);
            m1.z = fmaxf(m1.z, vb.z); m1.w = fmaxf(m1.w, vb.w);
        }
    }
    if ((hend - hstart) & 1) {           // tail row
        const float4* ra = base + (size_t)((hend - 1) * WW) * (CC / 4);
        #pragma unroll 4
        for (int x = 0; x < cols; x++) {
            float4 va = __ldg(ra); ra += (CC / 4);
            m0.x = fmaxf(m0.x, va.x); m0.y = fmaxf(m0.y, va.y);
            m0.z = fmaxf(m0.z, va.z); m0.w = fmaxf(m0.w, va.w);
        }
    }
    m0.x = fmaxf(m0.x, m1.x); m0.y = fmaxf(m0.y, m1.y);
    m0.z = fmaxf(m0.z, m1.z); m0.w = fmaxf(m0.w, m1.w);
    if (!any) m0 = make_float4(0.f, 0.f, 0.f, 0.f);
    stage4[pw][l] = m0;
    __syncthreads();

    // Copy out the 128x7 tile: out[(r*128+c)*49 + ph*7 + pw]
    const float* sf = (const float*)stage4;   // channel c of bin pw: pw*132 + c
    float* ob = out + (size_t)r * CC * (PHN * PWN) + ph * PWN;
    #pragma unroll
    for (int e = threadIdx.x; e < CC * PWN; e += 224) {
        int c   = e / PWN;
        int pww = e - c * PWN;
        ob[c * (PHN * PWN) + pww] = sf[pww * 132 + c];
    }
}

// ---------------------------------------------------------------------------
extern "C" void kernel_launch(void* const* d_in, const int* in_sizes, int n_in,
                              void* d_out, int out_size) {
    const float* feat = (const float*)d_in[0];   // (4,128,50,50)
    const float* rois = (const float*)d_in[1];   // (256,5)
    float* out = (float*)d_out;                  // (256,128,7,7)

    dim3 tb(32, 8);
    dim3 tg((HW + 31) / 32, CC / 32, NB);        // (79, 4, 4)
    nchw_to_nhwc<<<tg, tb>>>(feat);

    roipool_kernel<<<dim3(PHN, RR), 224>>>(rois, out);
}